// round 1
// baseline (speedup 1.0000x reference)
#include <cuda_runtime.h>
#include <cuda_bf16.h>
#include <cstdint>

// Problem constants
#define BATCH   2
#define SEQ     2048
#define EMBED   1024
#define NHEADS  16
#define HDIM    64
#define D3      (3 * EMBED)          // 3072
#define MROWS   (BATCH * SEQ)        // 4096

// Scratch (static device globals: allocation-free per harness rules)
__device__ float g_qkv[(size_t)MROWS * D3];     // (4096, 3072) = [q|k|v] per row
__device__ float g_attn[(size_t)MROWS * EMBED]; // (4096, 1024) attention output

// ---------------------------------------------------------------------------
// Tiled NT GEMM: C[M,N] = A[M,K] * B[N,K]^T   (both A and B are K-major)
// BM=BN=64, BK=16, 256 threads, 4x4 register microtile.
// ---------------------------------------------------------------------------
__device__ __forceinline__ void gemm_nt_body(const float* __restrict__ A,
                                             const float* __restrict__ B,
                                             float* __restrict__ C,
                                             int M, int N, int K)
{
    const int BM = 64, BN = 64, BK = 16;
    __shared__ float As[64][BK + 1];
    __shared__ float Bs[64][BK + 1];

    const int tid = threadIdx.x;
    const int tx = tid & 15;       // 0..15 -> N direction
    const int ty = tid >> 4;       // 0..15 -> M direction
    const int bm = blockIdx.y * BM;
    const int bn = blockIdx.x * BN;

    float acc[4][4];
#pragma unroll
    for (int i = 0; i < 4; i++)
#pragma unroll
        for (int j = 0; j < 4; j++) acc[i][j] = 0.f;

    for (int k0 = 0; k0 < K; k0 += BK) {
        // Load A tile (64x16) and B tile (64x16): 4 floats per thread each.
#pragma unroll
        for (int i = 0; i < (BM * BK) / 256; i++) {
            int idx = tid + i * 256;
            int r = idx >> 4, c = idx & 15;
            As[r][c] = A[(size_t)(bm + r) * K + k0 + c];
        }
#pragma unroll
        for (int i = 0; i < (BN * BK) / 256; i++) {
            int idx = tid + i * 256;
            int r = idx >> 4, c = idx & 15;
            Bs[r][c] = B[(size_t)(bn + r) * K + k0 + c];
        }
        __syncthreads();

#pragma unroll
        for (int kk = 0; kk < BK; kk++) {
            float a[4], b[4];
#pragma unroll
            for (int i = 0; i < 4; i++) a[i] = As[ty * 4 + i][kk];
#pragma unroll
            for (int j = 0; j < 4; j++) b[j] = Bs[tx * 4 + j][kk];
#pragma unroll
            for (int i = 0; i < 4; i++)
#pragma unroll
                for (int j = 0; j < 4; j++) acc[i][j] = fmaf(a[i], b[j], acc[i][j]);
        }
        __syncthreads();
    }

    // Vectorized epilogue: each thread writes 4 rows x float4
#pragma unroll
    for (int i = 0; i < 4; i++) {
        float4 v = make_float4(acc[i][0], acc[i][1], acc[i][2], acc[i][3]);
        *reinterpret_cast<float4*>(&C[(size_t)(bm + ty * 4 + i) * N + bn + tx * 4]) = v;
    }
}

__global__ __launch_bounds__(256) void qkv_gemm_kernel(const float* __restrict__ x,
                                                       const float* __restrict__ qkv_w)
{
    gemm_nt_body(x, qkv_w, g_qkv, MROWS, D3, EMBED);
}

__global__ __launch_bounds__(256) void out_gemm_kernel(const float* __restrict__ out_w,
                                                       float* __restrict__ out)
{
    gemm_nt_body(g_attn, out_w, out, MROWS, EMBED, EMBED);
}

// ---------------------------------------------------------------------------
// Flash attention, fp32.
// Q tile 64 rows x 64 dim; K/V tiles 32 rows. 256 threads (tx=16, ty=16).
// Per-thread: S fragment 4 rows x 2 cols, O fragment 4 rows x 4 cols.
// Row reductions via width-16 shuffles (rows owned by a ty group).
// ---------------------------------------------------------------------------
#define TQ 64
#define TK 32

__global__ __launch_bounds__(256) void attn_kernel()
{
    __shared__ float Qs[TQ][65];
    __shared__ float Ks[TK][65];
    __shared__ float Vs[TK][65];
    __shared__ float Ps[TQ][33];

    const int qi = blockIdx.x;     // 0..31 query tile
    const int h  = blockIdx.y;     // head
    const int b  = blockIdx.z;     // batch

    const int tid = threadIdx.x;
    const int tx = tid & 15;
    const int ty = tid >> 4;

    const int qbase = qi * TQ;
    const size_t rowbase = (size_t)b * SEQ;

    const float* qptr = g_qkv + rowbase * D3 + 0 * EMBED + h * HDIM;
    const float* kptr = g_qkv + rowbase * D3 + 1 * EMBED + h * HDIM;
    const float* vptr = g_qkv + rowbase * D3 + 2 * EMBED + h * HDIM;

    // Load Q tile: 64x64 floats
    for (int i = tid; i < TQ * HDIM; i += 256) {
        int r = i >> 6, c = i & 63;
        Qs[r][c] = qptr[(size_t)(qbase + r) * D3 + c];
    }

    float m[4], l[4], o[4][4];
#pragma unroll
    for (int i = 0; i < 4; i++) {
        m[i] = -1e30f;
        l[i] = 0.f;
#pragma unroll
        for (int j = 0; j < 4; j++) o[i][j] = 0.f;
    }

    const float scale = 0.125f;  // 1/sqrt(64)
    const int jmax = (qbase + TQ - 1) / TK;  // inclusive; == 2*qi + 1

    for (int j = 0; j <= jmax; j++) {
        const int kbase = j * TK;

        __syncthreads();  // previous PV reads of Ks/Vs/Ps complete
        for (int i = tid; i < TK * HDIM; i += 256) {
            int r = i >> 6, c = i & 63;
            Ks[r][c] = kptr[(size_t)(kbase + r) * D3 + c];
            Vs[r][c] = vptr[(size_t)(kbase + r) * D3 + c];
        }
        __syncthreads();

        // S = Q @ K^T (per-thread 4x2 fragment)
        float s0[4], s1[4];
#pragma unroll
        for (int i = 0; i < 4; i++) { s0[i] = 0.f; s1[i] = 0.f; }
        const int c0 = tx * 2, c1 = tx * 2 + 1;
#pragma unroll 8
        for (int k = 0; k < HDIM; k++) {
            float kv0 = Ks[c0][k];
            float kv1 = Ks[c1][k];
#pragma unroll
            for (int i = 0; i < 4; i++) {
                float q = Qs[ty * 4 + i][k];
                s0[i] = fmaf(q, kv0, s0[i]);
                s1[i] = fmaf(q, kv1, s1[i]);
            }
        }

        const bool need_mask = (kbase + TK - 1 > qbase);
#pragma unroll
        for (int i = 0; i < 4; i++) {
            float v0 = s0[i] * scale;
            float v1 = s1[i] * scale;
            if (need_mask) {
                int qg = qbase + ty * 4 + i;
                if (kbase + c0 > qg) v0 = -1e30f;
                if (kbase + c1 > qg) v1 = -1e30f;
            }
            // row max across the 16 tx lanes
            float mloc = fmaxf(v0, v1);
#pragma unroll
            for (int off = 1; off < 16; off <<= 1)
                mloc = fmaxf(mloc, __shfl_xor_sync(0xffffffffu, mloc, off, 16));
            float mnew = fmaxf(m[i], mloc);

            float p0 = __expf(v0 - mnew);
            float p1 = __expf(v1 - mnew);
            float rsum = p0 + p1;
#pragma unroll
            for (int off = 1; off < 16; off <<= 1)
                rsum += __shfl_xor_sync(0xffffffffu, rsum, off, 16);

            float factor = __expf(m[i] - mnew);
            l[i] = l[i] * factor + rsum;
            m[i] = mnew;
#pragma unroll
            for (int jj = 0; jj < 4; jj++) o[i][jj] *= factor;

            Ps[ty * 4 + i][c0] = p0;
            Ps[ty * 4 + i][c1] = p1;
        }
        __syncthreads();

        // O += P @ V  (per-thread 4 rows x 4 output dims, dims = tx*4..)
#pragma unroll 4
        for (int sidx = 0; sidx < TK; sidx++) {
            float p_[4], v_[4];
#pragma unroll
            for (int i = 0; i < 4; i++) p_[i] = Ps[ty * 4 + i][sidx];
#pragma unroll
            for (int jj = 0; jj < 4; jj++) v_[jj] = Vs[sidx][tx * 4 + jj];
#pragma unroll
            for (int i = 0; i < 4; i++)
#pragma unroll
                for (int jj = 0; jj < 4; jj++)
                    o[i][jj] = fmaf(p_[i], v_[jj], o[i][jj]);
        }
    }

    // Normalize and write to g_attn (B*T, 1024) layout: col = h*64 + d
#pragma unroll
    for (int i = 0; i < 4; i++) {
        float inv_l = 1.0f / l[i];
        float4 v = make_float4(o[i][0] * inv_l, o[i][1] * inv_l,
                               o[i][2] * inv_l, o[i][3] * inv_l);
        size_t row = rowbase + qbase + ty * 4 + i;
        *reinterpret_cast<float4*>(&g_attn[row * EMBED + h * HDIM + tx * 4]) = v;
    }
}

// ---------------------------------------------------------------------------
// Launch
// ---------------------------------------------------------------------------
extern "C" void kernel_launch(void* const* d_in, const int* in_sizes, int n_in,
                              void* d_out, int out_size)
{
    const float* x     = (const float*)d_in[0];  // (2, 2048, 1024)
    const float* qkv_w = (const float*)d_in[1];  // (3072, 1024)
    const float* out_w = (const float*)d_in[2];  // (1024, 1024)
    float* out = (float*)d_out;                  // (2, 2048, 1024)

    // 1) QKV projection: g_qkv = x @ qkv_w^T   (4096 x 3072)
    {
        dim3 grid(D3 / 64, MROWS / 64);
        qkv_gemm_kernel<<<grid, 256>>>(x, qkv_w);
    }

    // 2) Causal flash attention per (q-tile, head, batch)
    {
        dim3 grid(SEQ / TQ, NHEADS, BATCH);
        attn_kernel<<<grid, 256>>>();
    }

    // 3) Output projection: out = g_attn @ out_w^T  (4096 x 1024)
    {
        dim3 grid(EMBED / 64, MROWS / 64);
        out_gemm_kernel<<<grid, 256>>>(out_w, out);
    }
}

// round 3
// speedup vs baseline: 1.8070x; 1.8070x over previous
#include <cuda_runtime.h>
#include <cuda_bf16.h>
#include <cstdint>

// Problem constants
#define BATCH   2
#define SEQ     2048
#define EMBED   1024
#define NHEADS  16
#define HDIM    64
#define D3      (3 * EMBED)          // 3072
#define MROWS   (BATCH * SEQ)        // 4096

// ---------------------------------------------------------------------------
// Scratch (static device globals: allocation-free per harness rules)
// ---------------------------------------------------------------------------
__device__ float g_qkv [(size_t)MROWS * D3];      // (4096, 3072)
__device__ float g_attn[(size_t)MROWS * EMBED];   // (4096, 1024)

__device__ __align__(16) __nv_bfloat16 g_x_hi [(size_t)MROWS * EMBED];
__device__ __align__(16) __nv_bfloat16 g_x_lo [(size_t)MROWS * EMBED];
__device__ __align__(16) __nv_bfloat16 g_w1_hi[(size_t)D3 * EMBED];
__device__ __align__(16) __nv_bfloat16 g_w1_lo[(size_t)D3 * EMBED];
__device__ __align__(16) __nv_bfloat16 g_w2_hi[(size_t)EMBED * EMBED];
__device__ __align__(16) __nv_bfloat16 g_w2_lo[(size_t)EMBED * EMBED];
__device__ __align__(16) __nv_bfloat16 g_a_hi [(size_t)MROWS * EMBED];
__device__ __align__(16) __nv_bfloat16 g_a_lo [(size_t)MROWS * EMBED];

// ---------------------------------------------------------------------------
// PTX helpers (base sm_103-legal: ldmatrix / mma.sync / cp.async only)
// ---------------------------------------------------------------------------
__device__ __forceinline__ uint32_t smem_u32(const void* p) {
    uint32_t a;
    asm("{ .reg .u64 t; cvta.to.shared.u64 t, %1; cvt.u32.u64 %0, t; }" : "=r"(a) : "l"(p));
    return a;
}
__device__ __forceinline__ void cp_async16(uint32_t dst, const void* src) {
    asm volatile("cp.async.cg.shared.global [%0], [%1], 16;" :: "r"(dst), "l"(src));
}
__device__ __forceinline__ void cp_commit() {
    asm volatile("cp.async.commit_group;" ::: "memory");
}
template <int N>
__device__ __forceinline__ void cp_wait() {
    asm volatile("cp.async.wait_group %0;" :: "n"(N) : "memory");
}
__device__ __forceinline__ void ldsm_x4(uint32_t* r, uint32_t addr) {
    asm volatile("ldmatrix.sync.aligned.m8n8.x4.shared.b16 {%0,%1,%2,%3}, [%4];"
                 : "=r"(r[0]), "=r"(r[1]), "=r"(r[2]), "=r"(r[3]) : "r"(addr));
}
__device__ __forceinline__ void mma_bf16(float* c, const uint32_t* a, const uint32_t* b) {
    asm volatile(
        "mma.sync.aligned.m16n8k16.row.col.f32.bf16.bf16.f32 "
        "{%0,%1,%2,%3}, {%4,%5,%6,%7}, {%8,%9}, {%0,%1,%2,%3};"
        : "+f"(c[0]), "+f"(c[1]), "+f"(c[2]), "+f"(c[3])
        : "r"(a[0]), "r"(a[1]), "r"(a[2]), "r"(a[3]), "r"(b[0]), "r"(b[1]));
}

// ---------------------------------------------------------------------------
// fp32 -> (hi, lo) bf16 split
// ---------------------------------------------------------------------------
__global__ void split_kernel(const float* __restrict__ src,
                             __nv_bfloat16* __restrict__ hi,
                             __nv_bfloat16* __restrict__ lo, int n)
{
    int i = blockIdx.x * blockDim.x + threadIdx.x;
    if (i >= n) return;
    float v = src[i];
    __nv_bfloat16 h = __float2bfloat16(v);
    hi[i] = h;
    lo[i] = __float2bfloat16(v - __bfloat162float(h));
}

// ---------------------------------------------------------------------------
// 3xBF16 split GEMM via mma.sync: C[M,N] = A[M,K] * B[N,K]^T
// BM=BN=128, BK=32, 256 threads, warp tile 64x32, 2-stage cp.async pipeline.
// smem rows padded to 40 bf16 (80 B) -> conflict-free ldmatrix.
// ---------------------------------------------------------------------------
#define GBK      32
#define ROWB     80                       // bytes per smem row (32 bf16 + 8 pad)
#define TILE_SB  (128 * ROWB)             // 10240 per 128-row tile
#define STAGE_SB (4 * TILE_SB)            // Ah,Al,Bh,Bl = 40960
#define GEMM_SMEM (2 * STAGE_SB)          // 81920

__device__ __forceinline__ void load_stage_mma(uint32_t sbase,
                                               const __nv_bfloat16* __restrict__ Ah,
                                               const __nv_bfloat16* __restrict__ Al,
                                               const __nv_bfloat16* __restrict__ Bh,
                                               const __nv_bfloat16* __restrict__ Bl,
                                               int bm, int bn, int K, int k0, int tid)
{
#pragma unroll
    for (int rep = 0; rep < 2; rep++) {
        int s   = tid + rep * 256;        // 0..511
        int row = s >> 2;                 // 0..127
        int ch  = s & 3;                  // 16B chunk within 64B row payload
        uint32_t soff = (uint32_t)(row * ROWB + ch * 16);
        size_t ga = (size_t)(bm + row) * K + k0 + ch * 8;
        size_t gb = (size_t)(bn + row) * K + k0 + ch * 8;
        cp_async16(sbase + 0 * TILE_SB + soff, Ah + ga);
        cp_async16(sbase + 1 * TILE_SB + soff, Al + ga);
        cp_async16(sbase + 2 * TILE_SB + soff, Bh + gb);
        cp_async16(sbase + 3 * TILE_SB + soff, Bl + gb);
    }
}

__global__ __launch_bounds__(256, 1) void gemm3bf16_mma(
    const __nv_bfloat16* __restrict__ Ah, const __nv_bfloat16* __restrict__ Al,
    const __nv_bfloat16* __restrict__ Bh, const __nv_bfloat16* __restrict__ Bl,
    float* __restrict__ C, int M, int N, int K)
{
    extern __shared__ __align__(16) char dynsmem[];
    const uint32_t sb = smem_u32(dynsmem);

    const int tid  = threadIdx.x;
    const int lane = tid & 31;
    const int wid  = tid >> 5;
    const int wm   = wid >> 2;            // 0..1 (M)
    const int wn   = wid & 3;             // 0..3 (N)
    const int bm   = blockIdx.y * 128;
    const int bn   = blockIdx.x * 128;

    float acc[4][4][4];
#pragma unroll
    for (int i = 0; i < 4; i++)
#pragma unroll
        for (int j = 0; j < 4; j++)
#pragma unroll
            for (int k = 0; k < 4; k++) acc[i][j][k] = 0.f;

    const int NIT = K / GBK;

    load_stage_mma(sb, Ah, Al, Bh, Bl, bm, bn, K, 0, tid);
    cp_commit();

    // Per-lane ldmatrix address components
    const uint32_t a_row_in = (uint32_t)(lane & 15);          // row within 16-row tile
    const uint32_t a_kb     = (uint32_t)((lane >> 4) * 16);   // k-halve byte offset
    const int g  = lane >> 3;                                 // B x4 group
    const int br = lane & 7;
    const uint32_t b_row_in = (uint32_t)(((g >> 1) * 8) + br);
    const uint32_t b_kb     = (uint32_t)((g & 1) * 16);

    for (int it = 0; it < NIT; it++) {
        if (it + 1 < NIT) {
            load_stage_mma(sb + (uint32_t)((it + 1) & 1) * STAGE_SB,
                           Ah, Al, Bh, Bl, bm, bn, K, (it + 1) * GBK, tid);
            cp_commit();
            cp_wait<1>();
        } else {
            cp_wait<0>();
        }
        __syncthreads();

        const uint32_t st = sb + (uint32_t)(it & 1) * STAGE_SB;

#pragma unroll
        for (int ks = 0; ks < 2; ks++) {
            const uint32_t kb = (uint32_t)(ks * 32);  // 16 bf16 = 32 bytes

            uint32_t ah[4][4], al[4][4];
#pragma unroll
            for (int mt = 0; mt < 4; mt++) {
                uint32_t addr = st + (uint32_t)((wm * 64 + mt * 16) + a_row_in) * ROWB + kb + a_kb;
                ldsm_x4(ah[mt], addr);
                ldsm_x4(al[mt], addr + TILE_SB);
            }

            uint32_t bh[4][2], bl[4][2];
#pragma unroll
            for (int bt = 0; bt < 2; bt++) {
                uint32_t addr = st + 2 * TILE_SB +
                                (uint32_t)((wn * 32 + bt * 16) + b_row_in) * ROWB + kb + b_kb;
                uint32_t t4[4];
                ldsm_x4(t4, addr);
                bh[2 * bt][0] = t4[0]; bh[2 * bt][1] = t4[1];
                bh[2 * bt + 1][0] = t4[2]; bh[2 * bt + 1][1] = t4[3];
                ldsm_x4(t4, addr + TILE_SB);
                bl[2 * bt][0] = t4[0]; bl[2 * bt][1] = t4[1];
                bl[2 * bt + 1][0] = t4[2]; bl[2 * bt + 1][1] = t4[3];
            }

#pragma unroll
            for (int mt = 0; mt < 4; mt++)
#pragma unroll
                for (int nt = 0; nt < 4; nt++) {
                    mma_bf16(acc[mt][nt], ah[mt], bh[nt]);
                    mma_bf16(acc[mt][nt], ah[mt], bl[nt]);
                    mma_bf16(acc[mt][nt], al[mt], bh[nt]);
                }
        }
        __syncthreads();
    }

    // Epilogue
#pragma unroll
    for (int mt = 0; mt < 4; mt++) {
        int row = bm + wm * 64 + mt * 16 + (lane >> 2);
#pragma unroll
        for (int nt = 0; nt < 4; nt++) {
            int col = bn + wn * 32 + nt * 8 + (lane & 3) * 2;
            *reinterpret_cast<float2*>(&C[(size_t)row * N + col]) =
                make_float2(acc[mt][nt][0], acc[mt][nt][1]);
            *reinterpret_cast<float2*>(&C[(size_t)(row + 8) * N + col]) =
                make_float2(acc[mt][nt][2], acc[mt][nt][3]);
        }
    }
}

// ---------------------------------------------------------------------------
// Flash attention, fp32 SIMT
// ---------------------------------------------------------------------------
#define TQ 64
#define TK 32

__global__ __launch_bounds__(256) void attn_kernel()
{
    __shared__ float Qs[TQ][65];
    __shared__ float Ks[TK][65];
    __shared__ float Vs[TK][65];
    __shared__ float Ps[TQ][33];

    const int qi = blockIdx.x;
    const int h  = blockIdx.y;
    const int b  = blockIdx.z;

    const int tid = threadIdx.x;
    const int tx = tid & 15;
    const int ty = tid >> 4;

    const int qbase = qi * TQ;
    const size_t rowbase = (size_t)b * SEQ;

    const float* qptr = g_qkv + rowbase * D3 + 0 * EMBED + h * HDIM;
    const float* kptr = g_qkv + rowbase * D3 + 1 * EMBED + h * HDIM;
    const float* vptr = g_qkv + rowbase * D3 + 2 * EMBED + h * HDIM;

    for (int i = tid; i < TQ * 16; i += 256) {
        int r = i >> 4, c4 = (i & 15) * 4;
        float4 v = *reinterpret_cast<const float4*>(&qptr[(size_t)(qbase + r) * D3 + c4]);
        Qs[r][c4 + 0] = v.x; Qs[r][c4 + 1] = v.y; Qs[r][c4 + 2] = v.z; Qs[r][c4 + 3] = v.w;
    }

    float m[4], l[4], o[4][4];
#pragma unroll
    for (int i = 0; i < 4; i++) {
        m[i] = -1e30f; l[i] = 0.f;
#pragma unroll
        for (int j = 0; j < 4; j++) o[i][j] = 0.f;
    }

    const float scale = 0.125f;
    const int jmax = (qbase + TQ - 1) / TK;

    for (int j = 0; j <= jmax; j++) {
        const int kbase = j * TK;

        __syncthreads();
        for (int i = tid; i < TK * 16; i += 256) {
            int r = i >> 4, c4 = (i & 15) * 4;
            float4 kv = *reinterpret_cast<const float4*>(&kptr[(size_t)(kbase + r) * D3 + c4]);
            float4 vv = *reinterpret_cast<const float4*>(&vptr[(size_t)(kbase + r) * D3 + c4]);
            Ks[r][c4 + 0] = kv.x; Ks[r][c4 + 1] = kv.y; Ks[r][c4 + 2] = kv.z; Ks[r][c4 + 3] = kv.w;
            Vs[r][c4 + 0] = vv.x; Vs[r][c4 + 1] = vv.y; Vs[r][c4 + 2] = vv.z; Vs[r][c4 + 3] = vv.w;
        }
        __syncthreads();

        float s0[4], s1[4];
#pragma unroll
        for (int i = 0; i < 4; i++) { s0[i] = 0.f; s1[i] = 0.f; }
        const int c0 = tx * 2, c1 = tx * 2 + 1;
#pragma unroll 8
        for (int k = 0; k < HDIM; k++) {
            float kv0 = Ks[c0][k];
            float kv1 = Ks[c1][k];
#pragma unroll
            for (int i = 0; i < 4; i++) {
                float q = Qs[ty * 4 + i][k];
                s0[i] = fmaf(q, kv0, s0[i]);
                s1[i] = fmaf(q, kv1, s1[i]);
            }
        }

        const bool need_mask = (kbase + TK - 1 > qbase);
#pragma unroll
        for (int i = 0; i < 4; i++) {
            float v0 = s0[i] * scale;
            float v1 = s1[i] * scale;
            if (need_mask) {
                int qg = qbase + ty * 4 + i;
                if (kbase + c0 > qg) v0 = -1e30f;
                if (kbase + c1 > qg) v1 = -1e30f;
            }
            float mloc = fmaxf(v0, v1);
#pragma unroll
            for (int off = 1; off < 16; off <<= 1)
                mloc = fmaxf(mloc, __shfl_xor_sync(0xffffffffu, mloc, off, 16));
            float mnew = fmaxf(m[i], mloc);

            float p0 = __expf(v0 - mnew);
            float p1 = __expf(v1 - mnew);
            float rsum = p0 + p1;
#pragma unroll
            for (int off = 1; off < 16; off <<= 1)
                rsum += __shfl_xor_sync(0xffffffffu, rsum, off, 16);

            float factor = __expf(m[i] - mnew);
            l[i] = l[i] * factor + rsum;
            m[i] = mnew;
#pragma unroll
            for (int jj = 0; jj < 4; jj++) o[i][jj] *= factor;

            Ps[ty * 4 + i][c0] = p0;
            Ps[ty * 4 + i][c1] = p1;
        }
        __syncthreads();

#pragma unroll 4
        for (int sidx = 0; sidx < TK; sidx++) {
            float p_[4], v_[4];
#pragma unroll
            for (int i = 0; i < 4; i++) p_[i] = Ps[ty * 4 + i][sidx];
#pragma unroll
            for (int jj = 0; jj < 4; jj++) v_[jj] = Vs[sidx][tx * 4 + jj];
#pragma unroll
            for (int i = 0; i < 4; i++)
#pragma unroll
                for (int jj = 0; jj < 4; jj++)
                    o[i][jj] = fmaf(p_[i], v_[jj], o[i][jj]);
        }
    }

#pragma unroll
    for (int i = 0; i < 4; i++) {
        float inv_l = 1.0f / l[i];
        float4 v = make_float4(o[i][0] * inv_l, o[i][1] * inv_l,
                               o[i][2] * inv_l, o[i][3] * inv_l);
        size_t row = rowbase + qbase + ty * 4 + i;
        *reinterpret_cast<float4*>(&g_attn[row * EMBED + h * HDIM + tx * 4]) = v;
    }
}

// ---------------------------------------------------------------------------
// Launch
// ---------------------------------------------------------------------------
extern "C" void kernel_launch(void* const* d_in, const int* in_sizes, int n_in,
                              void* d_out, int out_size)
{
    const float* x     = (const float*)d_in[0];  // (2, 2048, 1024)
    const float* qkv_w = (const float*)d_in[1];  // (3072, 1024)
    const float* out_w = (const float*)d_in[2];  // (1024, 1024)
    float* out = (float*)d_out;                  // (2, 2048, 1024)

    static bool attr_done = false;
    if (!attr_done) {
        cudaFuncSetAttribute(gemm3bf16_mma, cudaFuncAttributeMaxDynamicSharedMemorySize, GEMM_SMEM);
        attr_done = true;
    }

    __nv_bfloat16 *xh, *xl, *w1h, *w1l, *w2h, *w2l, *ah, *al;
    float *qkv, *attn;
    cudaGetSymbolAddress((void**)&xh,  g_x_hi);
    cudaGetSymbolAddress((void**)&xl,  g_x_lo);
    cudaGetSymbolAddress((void**)&w1h, g_w1_hi);
    cudaGetSymbolAddress((void**)&w1l, g_w1_lo);
    cudaGetSymbolAddress((void**)&w2h, g_w2_hi);
    cudaGetSymbolAddress((void**)&w2l, g_w2_lo);
    cudaGetSymbolAddress((void**)&ah,  g_a_hi);
    cudaGetSymbolAddress((void**)&al,  g_a_lo);
    cudaGetSymbolAddress((void**)&qkv, g_qkv);
    cudaGetSymbolAddress((void**)&attn, g_attn);

    // 0) split inputs into bf16 hi/lo
    {
        int n1 = MROWS * EMBED;
        split_kernel<<<(n1 + 255) / 256, 256>>>(x, xh, xl, n1);
        int n2 = D3 * EMBED;
        split_kernel<<<(n2 + 255) / 256, 256>>>(qkv_w, w1h, w1l, n2);
        int n3 = EMBED * EMBED;
        split_kernel<<<(n3 + 255) / 256, 256>>>(out_w, w2h, w2l, n3);
    }

    // 1) QKV projection: g_qkv = x @ qkv_w^T   (4096 x 3072)
    {
        dim3 grid(D3 / 128, MROWS / 128);
        gemm3bf16_mma<<<grid, 256, GEMM_SMEM>>>(xh, xl, w1h, w1l, qkv, MROWS, D3, EMBED);
    }

    // 2) Causal flash attention
    {
        dim3 grid(SEQ / TQ, NHEADS, BATCH);
        attn_kernel<<<grid, 256>>>();
    }

    // 3) split attention output, then out projection
    {
        int n = MROWS * EMBED;
        split_kernel<<<(n + 255) / 256, 256>>>(attn, ah, al, n);
        dim3 grid(EMBED / 128, MROWS / 128);
        gemm3bf16_mma<<<grid, 256, GEMM_SMEM>>>(ah, al, w2h, w2l, out, MROWS, EMBED, EMBED);
    }
}

// round 4
// speedup vs baseline: 3.4092x; 1.8867x over previous
#include <cuda_runtime.h>
#include <cuda_bf16.h>
#include <cstdint>

// Problem constants
#define BATCH   2
#define SEQ     2048
#define EMBED   1024
#define NHEADS  16
#define HDIM    64
#define D3      (3 * EMBED)          // 3072
#define MROWS   (BATCH * SEQ)        // 4096

// ---------------------------------------------------------------------------
// Scratch (static device globals: allocation-free per harness rules)
// ---------------------------------------------------------------------------
__device__ float g_qkv [(size_t)MROWS * D3];      // (4096, 3072)
__device__ float g_attn[(size_t)MROWS * EMBED];   // (4096, 1024)

__device__ __align__(16) __nv_bfloat16 g_x_hi [(size_t)MROWS * EMBED];
__device__ __align__(16) __nv_bfloat16 g_x_lo [(size_t)MROWS * EMBED];
__device__ __align__(16) __nv_bfloat16 g_w1_hi[(size_t)D3 * EMBED];
__device__ __align__(16) __nv_bfloat16 g_w1_lo[(size_t)D3 * EMBED];
__device__ __align__(16) __nv_bfloat16 g_w2_hi[(size_t)EMBED * EMBED];
__device__ __align__(16) __nv_bfloat16 g_w2_lo[(size_t)EMBED * EMBED];
__device__ __align__(16) __nv_bfloat16 g_a_hi [(size_t)MROWS * EMBED];
__device__ __align__(16) __nv_bfloat16 g_a_lo [(size_t)MROWS * EMBED];

// ---------------------------------------------------------------------------
// PTX helpers (base sm_103-legal: ldmatrix / mma.sync / cp.async only)
// ---------------------------------------------------------------------------
__device__ __forceinline__ uint32_t smem_u32(const void* p) {
    uint32_t a;
    asm("{ .reg .u64 t; cvta.to.shared.u64 t, %1; cvt.u32.u64 %0, t; }" : "=r"(a) : "l"(p));
    return a;
}
__device__ __forceinline__ void cp_async16(uint32_t dst, const void* src) {
    asm volatile("cp.async.cg.shared.global [%0], [%1], 16;" :: "r"(dst), "l"(src));
}
__device__ __forceinline__ void cp_commit() {
    asm volatile("cp.async.commit_group;" ::: "memory");
}
template <int N>
__device__ __forceinline__ void cp_wait() {
    asm volatile("cp.async.wait_group %0;" :: "n"(N) : "memory");
}
__device__ __forceinline__ void ldsm_x4(uint32_t* r, uint32_t addr) {
    asm volatile("ldmatrix.sync.aligned.m8n8.x4.shared.b16 {%0,%1,%2,%3}, [%4];"
                 : "=r"(r[0]), "=r"(r[1]), "=r"(r[2]), "=r"(r[3]) : "r"(addr));
}
__device__ __forceinline__ void mma_bf16(float* c, const uint32_t* a, const uint32_t* b) {
    asm volatile(
        "mma.sync.aligned.m16n8k16.row.col.f32.bf16.bf16.f32 "
        "{%0,%1,%2,%3}, {%4,%5,%6,%7}, {%8,%9}, {%0,%1,%2,%3};"
        : "+f"(c[0]), "+f"(c[1]), "+f"(c[2]), "+f"(c[3])
        : "r"(a[0]), "r"(a[1]), "r"(a[2]), "r"(a[3]), "r"(b[0]), "r"(b[1]));
}
__device__ __forceinline__ uint32_t f2tf32(float f) {
    uint32_t r;
    asm("cvt.rna.tf32.f32 %0, %1;" : "=r"(r) : "f"(f));
    return r;
}
__device__ __forceinline__ void mma_tf32(float* c, const uint32_t* a, const uint32_t* b) {
    asm volatile(
        "mma.sync.aligned.m16n8k8.row.col.f32.tf32.tf32.f32 "
        "{%0,%1,%2,%3}, {%4,%5,%6,%7}, {%8,%9}, {%0,%1,%2,%3};"
        : "+f"(c[0]), "+f"(c[1]), "+f"(c[2]), "+f"(c[3])
        : "r"(a[0]), "r"(a[1]), "r"(a[2]), "r"(a[3]), "r"(b[0]), "r"(b[1]));
}

// ---------------------------------------------------------------------------
// fp32 -> (hi, lo) bf16 split, float4-vectorized
// ---------------------------------------------------------------------------
__global__ void split4_kernel(const float* __restrict__ src,
                              __nv_bfloat16* __restrict__ hi,
                              __nv_bfloat16* __restrict__ lo, int n4)
{
    int i = blockIdx.x * blockDim.x + threadIdx.x;
    if (i >= n4) return;
    float4 v = reinterpret_cast<const float4*>(src)[i];
    __nv_bfloat16 h0 = __float2bfloat16(v.x);
    __nv_bfloat16 h1 = __float2bfloat16(v.y);
    __nv_bfloat16 h2 = __float2bfloat16(v.z);
    __nv_bfloat16 h3 = __float2bfloat16(v.w);
    __nv_bfloat162* hp = reinterpret_cast<__nv_bfloat162*>(hi);
    __nv_bfloat162* lp = reinterpret_cast<__nv_bfloat162*>(lo);
    hp[2 * i]     = __nv_bfloat162(h0, h1);
    hp[2 * i + 1] = __nv_bfloat162(h2, h3);
    lp[2 * i]     = __nv_bfloat162(__float2bfloat16(v.x - __bfloat162float(h0)),
                                   __float2bfloat16(v.y - __bfloat162float(h1)));
    lp[2 * i + 1] = __nv_bfloat162(__float2bfloat16(v.z - __bfloat162float(h2)),
                                   __float2bfloat16(v.w - __bfloat162float(h3)));
}

// ---------------------------------------------------------------------------
// 3xBF16 split GEMM via mma.sync: C[M,N] = A[M,K] * B[N,K]^T  (unchanged, R3)
// ---------------------------------------------------------------------------
#define GBK      32
#define ROWB     80
#define TILE_SB  (128 * ROWB)
#define STAGE_SB (4 * TILE_SB)
#define GEMM_SMEM (2 * STAGE_SB)

__device__ __forceinline__ void load_stage_mma(uint32_t sbase,
                                               const __nv_bfloat16* __restrict__ Ah,
                                               const __nv_bfloat16* __restrict__ Al,
                                               const __nv_bfloat16* __restrict__ Bh,
                                               const __nv_bfloat16* __restrict__ Bl,
                                               int bm, int bn, int K, int k0, int tid)
{
#pragma unroll
    for (int rep = 0; rep < 2; rep++) {
        int s   = tid + rep * 256;
        int row = s >> 2;
        int ch  = s & 3;
        uint32_t soff = (uint32_t)(row * ROWB + ch * 16);
        size_t ga = (size_t)(bm + row) * K + k0 + ch * 8;
        size_t gb = (size_t)(bn + row) * K + k0 + ch * 8;
        cp_async16(sbase + 0 * TILE_SB + soff, Ah + ga);
        cp_async16(sbase + 1 * TILE_SB + soff, Al + ga);
        cp_async16(sbase + 2 * TILE_SB + soff, Bh + gb);
        cp_async16(sbase + 3 * TILE_SB + soff, Bl + gb);
    }
}

__global__ __launch_bounds__(256, 1) void gemm3bf16_mma(
    const __nv_bfloat16* __restrict__ Ah, const __nv_bfloat16* __restrict__ Al,
    const __nv_bfloat16* __restrict__ Bh, const __nv_bfloat16* __restrict__ Bl,
    float* __restrict__ C, int M, int N, int K)
{
    extern __shared__ __align__(16) char dynsmem[];
    const uint32_t sb = smem_u32(dynsmem);

    const int tid  = threadIdx.x;
    const int lane = tid & 31;
    const int wid  = tid >> 5;
    const int wm   = wid >> 2;
    const int wn   = wid & 3;
    const int bm   = blockIdx.y * 128;
    const int bn   = blockIdx.x * 128;

    float acc[4][4][4];
#pragma unroll
    for (int i = 0; i < 4; i++)
#pragma unroll
        for (int j = 0; j < 4; j++)
#pragma unroll
            for (int k = 0; k < 4; k++) acc[i][j][k] = 0.f;

    const int NIT = K / GBK;

    load_stage_mma(sb, Ah, Al, Bh, Bl, bm, bn, K, 0, tid);
    cp_commit();

    const uint32_t a_row_in = (uint32_t)(lane & 15);
    const uint32_t a_kb     = (uint32_t)((lane >> 4) * 16);
    const int g  = lane >> 3;
    const int br = lane & 7;
    const uint32_t b_row_in = (uint32_t)(((g >> 1) * 8) + br);
    const uint32_t b_kb     = (uint32_t)((g & 1) * 16);

    for (int it = 0; it < NIT; it++) {
        if (it + 1 < NIT) {
            load_stage_mma(sb + (uint32_t)((it + 1) & 1) * STAGE_SB,
                           Ah, Al, Bh, Bl, bm, bn, K, (it + 1) * GBK, tid);
            cp_commit();
            cp_wait<1>();
        } else {
            cp_wait<0>();
        }
        __syncthreads();

        const uint32_t st = sb + (uint32_t)(it & 1) * STAGE_SB;

#pragma unroll
        for (int ks = 0; ks < 2; ks++) {
            const uint32_t kb = (uint32_t)(ks * 32);

            uint32_t ah[4][4], al[4][4];
#pragma unroll
            for (int mt = 0; mt < 4; mt++) {
                uint32_t addr = st + (uint32_t)((wm * 64 + mt * 16) + a_row_in) * ROWB + kb + a_kb;
                ldsm_x4(ah[mt], addr);
                ldsm_x4(al[mt], addr + TILE_SB);
            }

            uint32_t bh[4][2], bl[4][2];
#pragma unroll
            for (int bt = 0; bt < 2; bt++) {
                uint32_t addr = st + 2 * TILE_SB +
                                (uint32_t)((wn * 32 + bt * 16) + b_row_in) * ROWB + kb + b_kb;
                uint32_t t4[4];
                ldsm_x4(t4, addr);
                bh[2 * bt][0] = t4[0]; bh[2 * bt][1] = t4[1];
                bh[2 * bt + 1][0] = t4[2]; bh[2 * bt + 1][1] = t4[3];
                ldsm_x4(t4, addr + TILE_SB);
                bl[2 * bt][0] = t4[0]; bl[2 * bt][1] = t4[1];
                bl[2 * bt + 1][0] = t4[2]; bl[2 * bt + 1][1] = t4[3];
            }

#pragma unroll
            for (int mt = 0; mt < 4; mt++)
#pragma unroll
                for (int nt = 0; nt < 4; nt++) {
                    mma_bf16(acc[mt][nt], ah[mt], bh[nt]);
                    mma_bf16(acc[mt][nt], ah[mt], bl[nt]);
                    mma_bf16(acc[mt][nt], al[mt], bh[nt]);
                }
        }
        __syncthreads();
    }

#pragma unroll
    for (int mt = 0; mt < 4; mt++) {
        int row = bm + wm * 64 + mt * 16 + (lane >> 2);
#pragma unroll
        for (int nt = 0; nt < 4; nt++) {
            int col = bn + wn * 32 + nt * 8 + (lane & 3) * 2;
            *reinterpret_cast<float2*>(&C[(size_t)row * N + col]) =
                make_float2(acc[mt][nt][0], acc[mt][nt][1]);
            *reinterpret_cast<float2*>(&C[(size_t)(row + 8) * N + col]) =
                make_float2(acc[mt][nt][2], acc[mt][nt][3]);
        }
    }
}

// ---------------------------------------------------------------------------
// TF32 tensor-core causal flash attention.
// CTA = (q-tile of 128, head, batch). 8 warps x 16 q-rows. TK=64 key tiles.
// smem (floats): Ksm[64][68] | Vsm[64][68] | Qsm[128][68] (tf32 bits) | Psm[128][68]
// ---------------------------------------------------------------------------
#define TQA   128
#define TKA   64
#define PADK  68
#define ATT_SMEM ((2 * 64 * PADK + 2 * 128 * PADK) * 4)   // 104448 bytes

__global__ __launch_bounds__(256, 2) void attn_tc_kernel()
{
    extern __shared__ float smf[];
    float* Ksm = smf;
    float* Vsm = smf + 64 * PADK;
    float* Qsm = smf + 2 * 64 * PADK;
    float* Psm = Qsm + 128 * PADK;

    const int tid  = threadIdx.x;
    const int lane = tid & 31;
    const int w    = tid >> 5;
    const int tr   = lane >> 2;      // 0..7
    const int tc   = lane & 3;       // 0..3

    const int qi = (int)gridDim.x - 1 - (int)blockIdx.x;   // big tiles first
    const int h  = blockIdx.y;
    const int b  = blockIdx.z;
    const int qb = qi * TQA;
    const size_t rowbase = (size_t)b * SEQ;

    const float* qptr = g_qkv + rowbase * D3 + h * HDIM;
    const float* kptr = qptr + EMBED;
    const float* vptr = qptr + 2 * EMBED;

    // Stage Q tile (128 x 64) into Qsm, pre-converted to tf32 bit patterns.
    for (int i = tid; i < 128 * 16; i += 256) {
        int r = i >> 4, c4 = (i & 15) * 4;
        float4 v = *reinterpret_cast<const float4*>(qptr + (size_t)(qb + r) * D3 + c4);
        float* dst = Qsm + r * PADK + c4;
        dst[0] = __uint_as_float(f2tf32(v.x));
        dst[1] = __uint_as_float(f2tf32(v.y));
        dst[2] = __uint_as_float(f2tf32(v.z));
        dst[3] = __uint_as_float(f2tf32(v.w));
    }

    const uint32_t ksb = smem_u32(Ksm);
    const uint32_t vsb = smem_u32(Vsm);

    float oacc[8][4];
#pragma unroll
    for (int nt = 0; nt < 8; nt++)
#pragma unroll
        for (int e = 0; e < 4; e++) oacc[nt][e] = 0.f;

    float m0 = -1e30f, m1 = -1e30f, l0 = 0.f, l1 = 0.f;

    const float CSC = 0.18033688f;   // (1/sqrt(64)) * log2(e)
    const int wrow  = qb + w * 16;   // warp's first q row (global)
    const int gr0   = wrow + tr;     // thread's row 0
    const int jmax  = (qb + TQA - 1) / TKA;   // = 2*qi + 1

    for (int j = 0; j <= jmax; j++) {
        const int kb = j * TKA;

        __syncthreads();   // previous tile's smem reads complete
        // cp.async load K and V tiles (64 x 64 each)
#pragma unroll
        for (int rep = 0; rep < 4; rep++) {
            int i = tid + rep * 256;         // 0..1023
            int r = i >> 4, c4 = (i & 15) * 4;
            uint32_t soff = (uint32_t)(r * PADK + c4) * 4;
            cp_async16(ksb + soff, kptr + (size_t)(kb + r) * D3 + c4);
            cp_async16(vsb + soff, vptr + (size_t)(kb + r) * D3 + c4);
        }
        cp_commit();
        cp_wait<0>();
        __syncthreads();

        if (kb <= wrow + 15) {   // warp tile not fully masked
            // ---- S = Q @ K^T ----
            float sacc[8][4];
#pragma unroll
            for (int nt = 0; nt < 8; nt++)
#pragma unroll
                for (int e = 0; e < 4; e++) sacc[nt][e] = 0.f;

#pragma unroll
            for (int kt = 0; kt < 8; kt++) {
                uint32_t qa[4];
                const float* qrow = Qsm + (size_t)(w * 16 + tr) * PADK + kt * 8 + tc;
                qa[0] = __float_as_uint(qrow[0]);
                qa[1] = __float_as_uint(qrow[8 * PADK]);
                qa[2] = __float_as_uint(qrow[4]);
                qa[3] = __float_as_uint(qrow[8 * PADK + 4]);
#pragma unroll
                for (int nt = 0; nt < 8; nt++) {
                    uint32_t bb[2];
                    const float* krow = Ksm + (size_t)(nt * 8 + tr) * PADK + kt * 8 + tc;
                    bb[0] = f2tf32(krow[0]);
                    bb[1] = f2tf32(krow[4]);
                    mma_tf32(sacc[nt], qa, bb);
                }
            }

            // ---- online softmax ----
            const bool need_mask = (kb + TKA - 1) > wrow;
            float mx0 = -1e30f, mx1 = -1e30f;
#pragma unroll
            for (int nt = 0; nt < 8; nt++) {
                int c0 = kb + nt * 8 + 2 * tc;
                float z0 = sacc[nt][0] * CSC;
                float z1 = sacc[nt][1] * CSC;
                float z2 = sacc[nt][2] * CSC;
                float z3 = sacc[nt][3] * CSC;
                if (need_mask) {
                    if (c0     > gr0) z0 = -1e30f;
                    if (c0 + 1 > gr0) z1 = -1e30f;
                    if (c0     > gr0 + 8) z2 = -1e30f;
                    if (c0 + 1 > gr0 + 8) z3 = -1e30f;
                }
                sacc[nt][0] = z0; sacc[nt][1] = z1;
                sacc[nt][2] = z2; sacc[nt][3] = z3;
                mx0 = fmaxf(mx0, fmaxf(z0, z1));
                mx1 = fmaxf(mx1, fmaxf(z2, z3));
            }
            mx0 = fmaxf(mx0, __shfl_xor_sync(0xffffffffu, mx0, 1));
            mx0 = fmaxf(mx0, __shfl_xor_sync(0xffffffffu, mx0, 2));
            mx1 = fmaxf(mx1, __shfl_xor_sync(0xffffffffu, mx1, 1));
            mx1 = fmaxf(mx1, __shfl_xor_sync(0xffffffffu, mx1, 2));

            float m0n = fmaxf(m0, mx0);
            float m1n = fmaxf(m1, mx1);
            float f0 = exp2f(m0 - m0n);
            float f1 = exp2f(m1 - m1n);

            float sum0 = 0.f, sum1 = 0.f;
            float* prow0 = Psm + (size_t)(w * 16 + tr) * PADK + 2 * tc;
            float* prow1 = prow0 + 8 * PADK;
#pragma unroll
            for (int nt = 0; nt < 8; nt++) {
                float p00 = exp2f(sacc[nt][0] - m0n);
                float p01 = exp2f(sacc[nt][1] - m0n);
                float p10 = exp2f(sacc[nt][2] - m1n);
                float p11 = exp2f(sacc[nt][3] - m1n);
                sum0 += p00 + p01;
                sum1 += p10 + p11;
                *reinterpret_cast<float2*>(prow0 + nt * 8) =
                    make_float2(__uint_as_float(f2tf32(p00)), __uint_as_float(f2tf32(p01)));
                *reinterpret_cast<float2*>(prow1 + nt * 8) =
                    make_float2(__uint_as_float(f2tf32(p10)), __uint_as_float(f2tf32(p11)));
            }
            sum0 += __shfl_xor_sync(0xffffffffu, sum0, 1);
            sum0 += __shfl_xor_sync(0xffffffffu, sum0, 2);
            sum1 += __shfl_xor_sync(0xffffffffu, sum1, 1);
            sum1 += __shfl_xor_sync(0xffffffffu, sum1, 2);

            l0 = l0 * f0 + sum0;
            l1 = l1 * f1 + sum1;
            m0 = m0n; m1 = m1n;
#pragma unroll
            for (int nt = 0; nt < 8; nt++) {
                oacc[nt][0] *= f0; oacc[nt][1] *= f0;
                oacc[nt][2] *= f1; oacc[nt][3] *= f1;
            }

            __syncwarp();

            // ---- O += P @ V ----
#pragma unroll
            for (int kt = 0; kt < 8; kt++) {
                uint32_t pa[4];
                const float* prow = Psm + (size_t)(w * 16 + tr) * PADK + kt * 8 + tc;
                pa[0] = __float_as_uint(prow[0]);
                pa[1] = __float_as_uint(prow[8 * PADK]);
                pa[2] = __float_as_uint(prow[4]);
                pa[3] = __float_as_uint(prow[8 * PADK + 4]);
#pragma unroll
                for (int nt = 0; nt < 8; nt++) {
                    uint32_t vb[2];
                    const float* vrow = Vsm + (size_t)(kt * 8 + tc) * PADK + nt * 8 + tr;
                    vb[0] = f2tf32(vrow[0]);
                    vb[1] = f2tf32(vrow[4 * PADK]);
                    mma_tf32(oacc[nt], pa, vb);
                }
            }
        }
    }

    // Epilogue: normalize, write to g_attn
    float il0 = 1.0f / l0;
    float il1 = 1.0f / l1;
    float* obase = g_attn + (size_t)(rowbase + gr0) * EMBED + h * HDIM + 2 * tc;
#pragma unroll
    for (int nt = 0; nt < 8; nt++) {
        *reinterpret_cast<float2*>(obase + nt * 8) =
            make_float2(oacc[nt][0] * il0, oacc[nt][1] * il0);
        *reinterpret_cast<float2*>(obase + 8 * EMBED + nt * 8) =
            make_float2(oacc[nt][2] * il1, oacc[nt][3] * il1);
    }
}

// ---------------------------------------------------------------------------
// Launch
// ---------------------------------------------------------------------------
extern "C" void kernel_launch(void* const* d_in, const int* in_sizes, int n_in,
                              void* d_out, int out_size)
{
    const float* x     = (const float*)d_in[0];
    const float* qkv_w = (const float*)d_in[1];
    const float* out_w = (const float*)d_in[2];
    float* out = (float*)d_out;

    static bool attr_done = false;
    if (!attr_done) {
        cudaFuncSetAttribute(gemm3bf16_mma, cudaFuncAttributeMaxDynamicSharedMemorySize, GEMM_SMEM);
        cudaFuncSetAttribute(attn_tc_kernel, cudaFuncAttributeMaxDynamicSharedMemorySize, ATT_SMEM);
        attr_done = true;
    }

    __nv_bfloat16 *xh, *xl, *w1h, *w1l, *w2h, *w2l, *ah, *al;
    float *qkv, *attn;
    cudaGetSymbolAddress((void**)&xh,  g_x_hi);
    cudaGetSymbolAddress((void**)&xl,  g_x_lo);
    cudaGetSymbolAddress((void**)&w1h, g_w1_hi);
    cudaGetSymbolAddress((void**)&w1l, g_w1_lo);
    cudaGetSymbolAddress((void**)&w2h, g_w2_hi);
    cudaGetSymbolAddress((void**)&w2l, g_w2_lo);
    cudaGetSymbolAddress((void**)&ah,  g_a_hi);
    cudaGetSymbolAddress((void**)&al,  g_a_lo);
    cudaGetSymbolAddress((void**)&qkv, g_qkv);
    cudaGetSymbolAddress((void**)&attn, g_attn);

    // 0) split inputs into bf16 hi/lo (float4 vectorized)
    {
        int n1 = MROWS * EMBED / 4;
        split4_kernel<<<(n1 + 255) / 256, 256>>>(x, xh, xl, n1);
        int n2 = D3 * EMBED / 4;
        split4_kernel<<<(n2 + 255) / 256, 256>>>(qkv_w, w1h, w1l, n2);
        int n3 = EMBED * EMBED / 4;
        split4_kernel<<<(n3 + 255) / 256, 256>>>(out_w, w2h, w2l, n3);
    }

    // 1) QKV projection
    {
        dim3 grid(D3 / 128, MROWS / 128);
        gemm3bf16_mma<<<grid, 256, GEMM_SMEM>>>(xh, xl, w1h, w1l, qkv, MROWS, D3, EMBED);
    }

    // 2) Causal flash attention (tf32 tensor cores)
    {
        dim3 grid(SEQ / TQA, NHEADS, BATCH);
        attn_tc_kernel<<<grid, 256, ATT_SMEM>>>();
    }

    // 3) split attention output, then out projection
    {
        int n = MROWS * EMBED / 4;
        split4_kernel<<<(n + 255) / 256, 256>>>(attn, ah, al, n);
        dim3 grid(EMBED / 128, MROWS / 128);
        gemm3bf16_mma<<<grid, 256, GEMM_SMEM>>>(ah, al, w2h, w2l, out, MROWS, EMBED, EMBED);
    }
}